// round 17
// baseline (speedup 1.0000x reference)
#include <cuda_runtime.h>
#include <cstdint>
#include <cstddef>

#define BATCH 8
#define P 2048
#define D 64
#define FEPS 0.1f
// log2(e)/eps
#define INV 14.426950408889634f
// eps*ln(2)
#define EPSLN2 0.06931471805599453f
#define NMAT ((size_t)BATCH * P * P)
#define NT4 4096             // 4-row tiles (streaming kernel)
#define NBLK 296             // streaming: 2 blocks per SM
#define TILE_BYTES 32768u    // 4 rows * 2048 * 4B
#define NSTAGE 3
#define GATE 30.0f
#define MARGIN 60.0f
#define KCAND 64
#define NITER 100
#define WARMUP 16
#define REBUILD 8

// ---------------- scratch (static device globals; no runtime allocation) ----
__device__ __align__(16) float g_u[BATCH * P];
__device__ __align__(16) float g_v[BATCH * P];
__device__ __align__(16) float g_ub[BATCH * P];   // u baseline (set by build pass)
__device__ __align__(16) float g_vb[BATCH * P];   // v baseline (set by snap)
__device__ float g_xn[BATCH * P];
__device__ float g_yn[BATCH * P];
__device__ float g_errp[BATCH * P];      // per-row |du|
__device__ float g_costp[BATCH * P];
__device__ int   g_done[2];
__device__ __align__(16) float4 g_ct4[NMAT / 4];               // C^T fp32
__device__ __align__(16) uint2 g_candU[(size_t)BATCH * P * KCAND]; // 8MB
__device__ __align__(16) uint2 g_candV[(size_t)BATCH * P * KCAND]; // 8MB
__device__ float g_cutU[BATCH * P];
__device__ float g_cutV[BATCH * P];
__device__ unsigned int g_DuD[BATCH];    // encoded max drift of u since baseline
__device__ unsigned int g_DvD[BATCH];    // encoded max drift of v since baseline

__device__ __forceinline__ float ex2f(float x) {
    float r; asm("ex2.approx.f32 %0, %1;" : "=f"(r) : "f"(x)); return r;
}
__device__ __forceinline__ float lg2f_(float x) {
    float r; asm("lg2.approx.f32 %0, %1;" : "=f"(r) : "f"(x)); return r;
}
__device__ __forceinline__ float eps_log_marginal() {
    return FEPS * logf(1.0f / 2048.0f + 1e-8f);
}
__device__ __forceinline__ uint32_t smem_u32(const void* p) {
    return (uint32_t)__cvta_generic_to_shared(p);
}
__device__ __forceinline__ void mbar_wait(uint32_t mbar, uint32_t phase) {
    asm volatile(
        "{\n\t.reg .pred P;\n\t"
        "W%=: mbarrier.try_wait.parity.acquire.cta.shared::cta.b64 P, [%0], %1;\n\t"
        "@!P bra W%=;\n\t}"
        :: "r"(mbar), "r"(phase) : "memory");
}
__device__ __forceinline__ void issue_copy(uint32_t smem_dst, const void* src,
                                           uint32_t mbar, uint32_t bytes) {
    asm volatile("mbarrier.arrive.expect_tx.shared.b64 _, [%0], %1;"
                 :: "r"(mbar), "r"(bytes) : "memory");
    asm volatile("cp.async.bulk.shared::cta.global.mbarrier::complete_tx::bytes "
                 "[%0], [%1], %2, [%3];"
                 :: "r"(smem_dst), "l"(src), "r"(bytes), "r"(mbar) : "memory");
}
__device__ __forceinline__ unsigned int fenc(float f) {
    unsigned int u = __float_as_uint(f);
    return (u & 0x80000000u) ? ~u : (u | 0x80000000u);
}
__device__ __forceinline__ float fdec(unsigned int u) {
    unsigned int v = (u & 0x80000000u) ? (u & 0x7fffffffu) : ~u;
    return __uint_as_float(v);
}

// ---------------- init --------------------------------------------------------
__global__ void k_init() {
    int i = blockIdx.x * blockDim.x + threadIdx.x;
    if (i < BATCH * P) { g_u[i] = 0.0f; g_v[i] = 0.0f; }
    if (i == 0) { g_done[0] = 0; g_done[1] = 0; }
}

// ---------------- squared norms (warp per point) ------------------------------
__global__ void k_norm(const float* __restrict__ x, const float* __restrict__ y) {
    int gw   = (blockIdx.x * blockDim.x + threadIdx.x) >> 5;
    int lane = threadIdx.x & 31;
    if (gw >= 2 * BATCH * P) return;
    bool isx = gw < BATCH * P;
    int p = isx ? gw : gw - BATCH * P;
    const float* src = isx ? x : y;
    float a0 = src[(size_t)p * D + lane];
    float a1 = src[(size_t)p * D + 32 + lane];
    float s = a0 * a0 + a1 * a1;
    #pragma unroll
    for (int o = 16; o; o >>= 1) s += __shfl_xor_sync(0xffffffffu, s, o);
    if (lane == 0) (isx ? g_xn : g_yn)[p] = s;
}

// ---------------- C = ||x||^2 + ||y||^2 - 2 x.y  (+ transposed copy) ----------
__global__ void k_costmat(const float* __restrict__ x, const float* __restrict__ y,
                          float* __restrict__ Cout) {
    __shared__ float xs[64][65];
    __shared__ float ys[64][65];
    int b  = blockIdx.z;
    int i0 = blockIdx.y * 64;
    int j0 = blockIdx.x * 64;
    int tid = threadIdx.x;

    const float* xb = x + ((size_t)b * P + i0) * D;
    const float* yb = y + ((size_t)b * P + j0) * D;
    #pragma unroll
    for (int idx = tid; idx < 4096; idx += 256) {
        int p = idx >> 6, d = idx & 63;
        xs[d][p] = xb[(size_t)p * D + d];
        ys[d][p] = yb[(size_t)p * D + d];
    }
    __syncthreads();

    int tx = tid & 15, ty = tid >> 4;
    float acc[4][4];
    #pragma unroll
    for (int r = 0; r < 4; r++)
        #pragma unroll
        for (int c = 0; c < 4; c++) acc[r][c] = 0.0f;

    #pragma unroll 8
    for (int k = 0; k < 64; k++) {
        float rx[4], ry[4];
        #pragma unroll
        for (int r = 0; r < 4; r++) rx[r] = xs[k][ty * 4 + r];
        #pragma unroll
        for (int c = 0; c < 4; c++) ry[c] = ys[k][tx * 4 + c];
        #pragma unroll
        for (int r = 0; r < 4; r++)
            #pragma unroll
            for (int c = 0; c < 4; c++) acc[r][c] = fmaf(rx[r], ry[c], acc[r][c]);
    }

    float xnr[4], ynr[4];
    #pragma unroll
    for (int r = 0; r < 4; r++) xnr[r] = g_xn[b * P + i0 + ty * 4 + r];
    #pragma unroll
    for (int c = 0; c < 4; c++) ynr[c] = g_yn[b * P + j0 + tx * 4 + c];

    float val[4][4];
    #pragma unroll
    for (int r = 0; r < 4; r++)
        #pragma unroll
        for (int c = 0; c < 4; c++)
            val[r][c] = xnr[r] + ynr[c] - 2.0f * acc[r][c];

    #pragma unroll
    for (int r = 0; r < 4; r++) {
        int row = i0 + ty * 4 + r;
        float4 v4 = make_float4(val[r][0], val[r][1], val[r][2], val[r][3]);
        *reinterpret_cast<float4*>(Cout + ((size_t)b * P + row) * P + j0 + tx * 4) = v4;
    }

    __syncthreads();
    #pragma unroll
    for (int r = 0; r < 4; r++)
        #pragma unroll
        for (int c = 0; c < 4; c++)
            xs[ty * 4 + r][tx * 4 + c] = val[r][c];
    __syncthreads();
    float* CT = (float*)g_ct4;
    #pragma unroll
    for (int idx = tid; idx < 4096; idx += 256) {
        int jj = idx >> 6, ii = idx & 63;
        CT[((size_t)b * P + (j0 + jj)) * P + (i0 + ii)] = xs[ii][jj];
    }
}

// ---------------- streaming row-LSE pass (optionally building cand lists) -----
template<bool UPASS, bool BUILD>
__global__ void __launch_bounds__(256, 2) k_lse_pipe(const float* __restrict__ Cg, int par) {
    if (g_done[par]) {
        if (!UPASS && blockIdx.x == 0 && threadIdx.x == 0) g_done[par ^ 1] = 1;
        return;
    }
    const float* M    = UPASS ? Cg : (const float*)g_ct4;
    const float* wv   = UPASS ? g_v : g_u;
    float*       outv = UPASS ? g_u : g_v;
    uint2*       cand = UPASS ? g_candU : g_candV;
    float*       cutw = UPASS ? g_cutU : g_cutV;

    extern __shared__ __align__(128) float tile[];
    __shared__ float sm[8];
    __shared__ float ss[8];
    __shared__ float red[256];
    __shared__ int scnt[4];
    __shared__ __align__(8) unsigned long long mbars[NSTAGE];

    int tid = threadIdx.x, lane = tid & 31, warp = tid >> 5;
    int row4 = warp >> 1;
    int half = warp & 1;
    int t0 = (int)(((long long)blockIdx.x * NT4) / NBLK);
    int t1 = (int)(((long long)(blockIdx.x + 1) * NT4) / NBLK);

    uint32_t mb0 = smem_u32(&mbars[0]);
    if (tid == 0) {
        #pragma unroll
        for (int s = 0; s < NSTAGE; s++)
            asm volatile("mbarrier.init.shared.b64 [%0], 1;" :: "r"(mb0 + 8 * s) : "memory");
    }
    if (BUILD && tid < 4) scnt[tid] = 0;
    __syncthreads();
    if (tid == 0) {
        #pragma unroll
        for (int s = 0; s < NSTAGE; s++)
            if (t0 + s < t1)
                issue_copy(smem_u32(tile) + s * TILE_BYTES,
                           M + (size_t)(t0 + s) * (4 * P), mb0 + 8 * s, TILE_BYTES);
    }

    if (!UPASS && blockIdx.x == 0) {
        float e = 0.0f;
        for (int t = tid; t < BATCH * P; t += 256) e += g_errp[t];
        red[tid] = e;
        __syncthreads();
        for (int o = 128; o; o >>= 1) {
            if (tid < o) red[tid] += red[tid + o];
            __syncthreads();
        }
        if (tid == 0)
            g_done[par ^ 1] = (red[0] * (1.0f / BATCH) < 0.1f) ? 1 : 0;
    }

    float4 tv[8];
    int cur_b = -1;
    float wdm = -3.4e38f;        // per-thread (half0/lane0) drift max, v build
    int phase[NSTAGE];
    #pragma unroll
    for (int s = 0; s < NSTAGE; s++) phase[s] = 0;

    for (int k = t0; k < t1; k++) {
        int b = k >> 9;
        if (b != cur_b) {
            if (BUILD && !UPASS && cur_b >= 0 && half == 0 && lane == 0) {
                atomicMax(&g_DvD[cur_b], fenc(wdm));   // flush drift for old batch
                wdm = -3.4e38f;
            }
            const float4* vb4 = reinterpret_cast<const float4*>(wv + b * P);
            #pragma unroll
            for (int q = 0; q < 8; q++) {
                float4 t = vb4[half * 256 + lane + 32 * q];
                tv[q] = make_float4(t.x * INV, t.y * INV, t.z * INV, t.w * INV);
            }
            cur_b = b;
        }

        int s = (k - t0) % NSTAGE;
        mbar_wait(mb0 + 8 * s, (uint32_t)phase[s]);
        phase[s] ^= 1;

        const float4* R = reinterpret_cast<const float4*>(tile + s * 8192)
                          + row4 * 512 + half * 256;

        float lm = -3.4e38f;
        #pragma unroll
        for (int q = 0; q < 8; q++) {
            float4 c = R[lane + q * 32];
            float4 t = tv[q];
            lm = fmaxf(lm, fmaf(c.x, -INV, t.x));
            lm = fmaxf(lm, fmaf(c.y, -INV, t.y));
            lm = fmaxf(lm, fmaf(c.z, -INV, t.z));
            lm = fmaxf(lm, fmaf(c.w, -INV, t.w));
        }
        float mh = lm;
        #pragma unroll
        for (int o = 16; o; o >>= 1) mh = fmaxf(mh, __shfl_xor_sync(0xffffffffu, mh, o));
        if (lane == 0) sm[warp] = mh;
        __syncthreads();
        float m = fmaxf(sm[warp], sm[warp ^ 1]);
        int gr = k * 4 + row4;          // global row index

        float ls = 0.0f;
        if (BUILD) {
            // unconditional scan: exp2 sum + candidate selection
            float thr = m - MARGIN;
            #pragma unroll
            for (int q = 0; q < 8; q++) {
                float4 c = R[lane + q * 32];
                float4 t = tv[q];
                int jb = 4 * (half * 256 + lane + 32 * q);
                float w0 = fmaf(c.x, -INV, t.x);
                float w1 = fmaf(c.y, -INV, t.y);
                float w2 = fmaf(c.z, -INV, t.z);
                float w3 = fmaf(c.w, -INV, t.w);
                ls += ex2f(fminf(w0, 0.0f) - m + fmaxf(w0 - 0.0f, 0.0f));  // placeholder avoided below
                ls = ls;  // (we compute ls plainly below)
                ls -= ex2f(fminf(w0, 0.0f) - m + fmaxf(w0 - 0.0f, 0.0f));
                ls += ex2f(w0 - m) + ex2f(w1 - m) + ex2f(w2 - m) + ex2f(w3 - m);
                if (w0 > thr) { int p = atomicAdd(&scnt[row4], 1); if (p < KCAND) cand[(size_t)gr * KCAND + p] = make_uint2(__float_as_uint(c.x), jb + 0); }
                if (w1 > thr) { int p = atomicAdd(&scnt[row4], 1); if (p < KCAND) cand[(size_t)gr * KCAND + p] = make_uint2(__float_as_uint(c.y), jb + 1); }
                if (w2 > thr) { int p = atomicAdd(&scnt[row4], 1); if (p < KCAND) cand[(size_t)gr * KCAND + p] = make_uint2(__float_as_uint(c.z), jb + 2); }
                if (w3 > thr) { int p = atomicAdd(&scnt[row4], 1); if (p < KCAND) cand[(size_t)gr * KCAND + p] = make_uint2(__float_as_uint(c.w), jb + 3); }
            }
        } else {
            if (lm > m - GATE) {
                #pragma unroll
                for (int q = 0; q < 8; q++) {
                    float4 c = R[lane + q * 32];
                    float4 t = tv[q];
                    ls += ex2f(fmaf(c.x, -INV, t.x) - m);
                    ls += ex2f(fmaf(c.y, -INV, t.y) - m);
                    ls += ex2f(fmaf(c.z, -INV, t.z) - m);
                    ls += ex2f(fmaf(c.w, -INV, t.w) - m);
                }
            }
        }
        #pragma unroll
        for (int o = 16; o; o >>= 1) ls += __shfl_xor_sync(0xffffffffu, ls, o);
        if (lane == 0) ss[warp] = ls;
        __syncthreads();                 // all stage-s reads complete; counters settled

        if (half == 0 && lane == 0) {
            float tot = ss[warp] + ss[warp | 1];
            float nv = eps_log_marginal() - EPSLN2 * (m + lg2f_(tot));
            if (UPASS) {
                float old = outv[gr];
                outv[gr] = nv;
                g_errp[gr] = fabsf(nv - old);
                if (BUILD) g_ub[gr] = nv;           // drift baseline for candV
            } else {
                outv[gr] = nv;
                if (BUILD) wdm = fmaxf(wdm, nv - g_vb[gr]);  // v drift vs candU baseline
            }
            if (BUILD) cutw[gr] = (scnt[row4] <= KCAND) ? (m - MARGIN) : 3.0e38f;
        }
        if (tid == 0 && k + NSTAGE < t1)
            issue_copy(smem_u32(tile) + s * TILE_BYTES,
                       M + (size_t)(k + NSTAGE) * (4 * P), mb0 + 8 * s, TILE_BYTES);
        if (BUILD) {
            __syncthreads();             // cutw/counters read complete
            int cnt = scnt[row4];
            for (int p = cnt + half * 32 + lane; p < KCAND; p += 64)
                cand[(size_t)gr * KCAND + p] = make_uint2(__float_as_uint(3.0e38f), 0);
            __syncthreads();
            if (tid < 4) scnt[tid] = 0;  // visible before next tile's pushes (next barrier)
        }
    }
    if (BUILD && !UPASS && cur_b >= 0 && half == 0 && lane == 0)
        atomicMax(&g_DvD[cur_b], fenc(wdm));
}

// ---------------- snapshot v baseline + drift reset ---------------------------
__global__ void k_snap(int par) {
    if (g_done[par]) return;
    int i = blockIdx.x * blockDim.x + threadIdx.x;
    if (i < BATCH * P) g_vb[i] = g_v[i];
    if (i < BATCH) { g_DuD[i] = fenc(0.0f); g_DvD[i] = fenc(0.0f); }
}

// ---------------- candidate fast path with inline per-row exact fallback ------
template<bool UPASS>
__global__ void __launch_bounds__(256) k_candfix(const float4* __restrict__ Cg4, int par) {
    if (g_done[par]) {
        if (!UPASS && blockIdx.x == 0 && threadIdx.x == 0) g_done[par ^ 1] = 1;
        return;
    }
    __shared__ __align__(16) float vs[P];
    __shared__ float red[256];
    __shared__ float sdm[8];

    int tid = threadIdx.x, lane = tid & 31, warp = tid >> 5;
    int base = blockIdx.x * 32;          // 32 rows per block
    int b = blockIdx.x >> 6;             // 64 blocks per batch

    const uint2*  cand = UPASS ? g_candU : g_candV;
    const float*  cutw = UPASS ? g_cutU : g_cutV;
    const float*  dual = UPASS ? g_v : g_u;
    const float*  snap = UPASS ? g_ub : g_vb;
    const float4* M4   = UPASS ? Cg4 : (const float4*)g_ct4;
    float*        outv = UPASS ? g_u : g_v;
    float Din = fdec(UPASS ? g_DvD[b] : g_DuD[b]);

    if (!UPASS && blockIdx.x == 0) {
        float e = 0.0f;
        for (int t = tid; t < BATCH * P; t += 256) e += g_errp[t];
        red[tid] = e;
        __syncthreads();
        for (int o = 128; o; o >>= 1) {
            if (tid < o) red[tid] += red[tid + o];
            __syncthreads();
        }
        if (tid == 0)
            g_done[par ^ 1] = (red[0] * (1.0f / BATCH) < 0.1f) ? 1 : 0;
    }

    const float4* db4 = reinterpret_cast<const float4*>(dual + b * P);
    float4* vs4 = reinterpret_cast<float4*>(vs);
    for (int j = tid; j < 512; j += 256) {
        float4 t = db4[j];
        vs4[j] = make_float4(t.x * INV, t.y * INV, t.z * INV, t.w * INV);
    }
    __syncthreads();

    float wdm = -3.4e38f;
    #pragma unroll 1
    for (int r = 0; r < 4; r++) {
        int row = base + r * 8 + warp;
        uint2 e0 = cand[(size_t)row * KCAND + lane];
        uint2 e1 = cand[(size_t)row * KCAND + 32 + lane];
        float w0 = vs[e0.y] - __uint_as_float(e0.x) * INV;
        float w1 = vs[e1.y] - __uint_as_float(e1.x) * INV;
        float lm = fmaxf(w0, w1);
        float m = lm;
        #pragma unroll
        for (int o = 16; o; o >>= 1) m = fmaxf(m, __shfl_xor_sync(0xffffffffu, m, o));

        float nv;
        bool dirty = (cutw[row] + INV * Din > m - GATE);
        if (!dirty) {
            float ls = 0.0f;
            if (lm > m - GATE) ls = ex2f(w0 - m) + ex2f(w1 - m);
            #pragma unroll
            for (int o = 16; o; o >>= 1) ls += __shfl_xor_sync(0xffffffffu, ls, o);
            nv = eps_log_marginal() - EPSLN2 * (m + lg2f_(ls));
        } else {
            // exact per-row fallback: full row from global (warp-wide)
            const float4* R = M4 + (size_t)row * 512;
            float qm[16];
            #pragma unroll
            for (int q = 0; q < 16; q++) {
                float4 c = __ldg(&R[lane + 32 * q]);
                float4 t = vs4[lane + 32 * q];
                float x0 = fmaf(c.x, -INV, t.x);
                float x1 = fmaf(c.y, -INV, t.y);
                float x2 = fmaf(c.z, -INV, t.z);
                float x3 = fmaf(c.w, -INV, t.w);
                qm[q] = fmaxf(fmaxf(x0, x1), fmaxf(x2, x3));
            }
            float flm = qm[0];
            #pragma unroll
            for (int q = 1; q < 16; q++) flm = fmaxf(flm, qm[q]);
            float fm = flm;
            #pragma unroll
            for (int o = 16; o; o >>= 1) fm = fmaxf(fm, __shfl_xor_sync(0xffffffffu, fm, o));
            float ls = 0.0f;
            if (flm > fm - GATE) {
                #pragma unroll
                for (int q = 0; q < 16; q++) {
                    if (qm[q] > fm - GATE) {
                        float4 c = __ldg(&R[lane + 32 * q]);
                        float4 t = vs4[lane + 32 * q];
                        ls += ex2f(fmaf(c.x, -INV, t.x) - fm);
                        ls += ex2f(fmaf(c.y, -INV, t.y) - fm);
                        ls += ex2f(fmaf(c.z, -INV, t.z) - fm);
                        ls += ex2f(fmaf(c.w, -INV, t.w) - fm);
                    }
                }
            }
            #pragma unroll
            for (int o = 16; o; o >>= 1) ls += __shfl_xor_sync(0xffffffffu, ls, o);
            nv = eps_log_marginal() - EPSLN2 * (fm + lg2f_(ls));
        }

        if (lane == 0) {
            float old = outv[row];
            outv[row] = nv;
            if (UPASS) g_errp[row] = fabsf(nv - old);
            wdm = fmaxf(wdm, nv - snap[row]);
        }
    }
    if (lane == 0) sdm[warp] = wdm;
    __syncthreads();
    if (tid == 0) {
        float dm = sdm[0];
        #pragma unroll
        for (int i2 = 1; i2 < 8; i2++) dm = fmaxf(dm, sdm[i2]);
        atomicMax(UPASS ? &g_DuD[b] : &g_DvD[b], fenc(dm));
    }
}

// ---------------- pi = exp((u+v-C)/eps), partial cost -------------------------
__global__ void __launch_bounds__(256) k_pi(const float4* __restrict__ C4,
                                            float4* __restrict__ pi4) {
    __shared__ __align__(16) float uvw[2048];
    __shared__ float sacc[256];
    int r = blockIdx.x, b = r >> 11, tid = threadIdx.x;
    float ug = g_u[r] * INV;
    for (int j = tid; j < 2048; j += 256) uvw[j] = fmaf(g_v[b * P + j], INV, ug);
    __syncthreads();

    const float4* Crow = C4 + (size_t)r * 512;
    float4* prow = pi4 + (size_t)r * 512;
    const float4* uvw4 = reinterpret_cast<const float4*>(uvw);
    float acc = 0.0f;
    #pragma unroll 2
    for (int j4 = tid; j4 < 512; j4 += 256) {
        float4 c = Crow[j4];
        float4 t = uvw4[j4];
        float4 p;
        p.x = ex2f(fmaf(c.x, -INV, t.x));
        p.y = ex2f(fmaf(c.y, -INV, t.y));
        p.z = ex2f(fmaf(c.z, -INV, t.z));
        p.w = ex2f(fmaf(c.w, -INV, t.w));
        prow[j4] = p;
        acc = fmaf(p.x, c.x, fmaf(p.y, c.y, fmaf(p.z, c.z, fmaf(p.w, c.w, acc))));
    }
    sacc[tid] = acc;
    __syncthreads();
    for (int o = 128; o; o >>= 1) {
        if (tid < o) sacc[tid] += sacc[tid + o];
        __syncthreads();
    }
    if (tid == 0) g_costp[r] = sacc[0];
}

__global__ void k_costred(float* __restrict__ costOut) {
    __shared__ float sb[256];
    int b = blockIdx.x;
    float e = 0.0f;
    for (int t = threadIdx.x; t < P; t += 256) e += g_costp[b * P + t];
    sb[threadIdx.x] = e;
    __syncthreads();
    for (int o = 128; o; o >>= 1) {
        if (threadIdx.x < o) sb[threadIdx.x] += sb[threadIdx.x + o];
        __syncthreads();
    }
    if (threadIdx.x == 0) costOut[b] = sb[0];
}

// ---------------- launch ------------------------------------------------------
extern "C" void kernel_launch(void* const* d_in, const int* in_sizes, int n_in,
                              void* d_out, int out_size) {
    (void)in_sizes; (void)n_in; (void)out_size;
    const float* x = (const float*)d_in[0];
    const float* y = (const float*)d_in[1];
    float* out  = (float*)d_out;
    float* cost = out;                      // [8]
    float* pi   = out + 8;                  // [8,2048,2048]
    float* Cm   = out + 8 + NMAT;           // [8,2048,2048]

    cudaFuncSetAttribute(k_lse_pipe<true, false>,
                         cudaFuncAttributeMaxDynamicSharedMemorySize, NSTAGE * (int)TILE_BYTES);
    cudaFuncSetAttribute(k_lse_pipe<false, false>,
                         cudaFuncAttributeMaxDynamicSharedMemorySize, NSTAGE * (int)TILE_BYTES);
    cudaFuncSetAttribute(k_lse_pipe<true, true>,
                         cudaFuncAttributeMaxDynamicSharedMemorySize, NSTAGE * (int)TILE_BYTES);
    cudaFuncSetAttribute(k_lse_pipe<false, true>,
                         cudaFuncAttributeMaxDynamicSharedMemorySize, NSTAGE * (int)TILE_BYTES);

    k_init<<<64, 256>>>();
    k_norm<<<4096, 256>>>(x, y);
    dim3 cg(32, 32, 8);
    k_costmat<<<cg, 256>>>(x, y, Cm);

    // warmup: streaming iterations (duals take shape)
    for (int k = 0; k < WARMUP; k++) {
        int par = k & 1;
        k_lse_pipe<true,  false><<<NBLK, 256, NSTAGE * TILE_BYTES>>>(Cm, par);
        k_lse_pipe<false, false><<<NBLK, 256, NSTAGE * TILE_BYTES>>>(Cm, par);
    }

    // candidate mode; rebuild iterations ARE streaming iterations (BUILD=true)
    for (int k = WARMUP; k < NITER; k++) {
        int par = k & 1;
        if (((k - WARMUP) % REBUILD) == 0) {
            k_snap<<<64, 256>>>(par);
            k_lse_pipe<true,  true><<<NBLK, 256, NSTAGE * TILE_BYTES>>>(Cm, par);
            k_lse_pipe<false, true><<<NBLK, 256, NSTAGE * TILE_BYTES>>>(Cm, par);
        } else {
            k_candfix<true ><<<512, 256>>>((const float4*)Cm, par);
            k_candfix<false><<<512, 256>>>((const float4*)Cm, par);
        }
    }

    k_pi<<<16384, 256>>>((const float4*)Cm, (float4*)pi);
    k_costred<<<8, 256>>>(cost);
}